// round 7
// baseline (speedup 1.0000x reference)
#include <cuda_runtime.h>
#include <cuda_pipeline.h>
#include <math.h>

#define B 64
#define P 8732
#define M 16
#define C 81
#define EPSF 1e-7f
#define L2E 1.4426950408889634f
#define LN2 0.6931471805599453f

// ---------------- device scratch (static globals: no allocation) ----------------
__device__ float               g_ovl[B * P];
__device__ unsigned char       g_obj[B * P];
__device__ float               g_conf_neg[B * P];
__device__ unsigned long long  g_best[B * M];   // packed (iou_bits<<32)|~prior_idx
__device__ int                 g_n_pos[B];
__device__ double              g_conf_pos[B];
__device__ double              g_loc_pb[B];
__device__ double              g_hard_pb[B];
__device__ unsigned int        g_done;
__device__ unsigned int        g_iou_done;

// ---------------- helpers ----------------
__device__ __forceinline__ float ex2f(float x) {
    float y; asm("ex2.approx.ftz.f32 %0, %1;" : "=f"(y) : "f"(x)); return y;
}
__device__ __forceinline__ float lg2f(float x) {
    float y; asm("lg2.approx.ftz.f32 %0, %1;" : "=f"(y) : "f"(x)); return y;
}

__device__ __forceinline__ double blockReduceSumD(double v) {
    __shared__ double sh[32];
    int lane = threadIdx.x & 31, wid = threadIdx.x >> 5;
    #pragma unroll
    for (int o = 16; o; o >>= 1) v += __shfl_down_sync(0xffffffffu, v, o);
    if (lane == 0) sh[wid] = v;
    __syncthreads();
    int nw = (blockDim.x + 31) >> 5;
    v = (threadIdx.x < (unsigned)nw) ? sh[threadIdx.x] : 0.0;
    if (wid == 0) {
        #pragma unroll
        for (int o = 16; o; o >>= 1) v += __shfl_down_sync(0xffffffffu, v, o);
    }
    __syncthreads();
    return v;  // valid in thread 0
}

// ---------------- K1: one prior per thread; REDUX per-object argmax; fused scatter+init ----------------
#define IOU_TPB    256
#define IOU_NCHUNK ((P + IOU_TPB - 1) / IOU_TPB)   // 35
#define IOU_GRID   (B * IOU_NCHUNK)                 // 2240
__global__ void __launch_bounds__(IOU_TPB)
k_iou(const float4* __restrict__ boxes,
      const float4* __restrict__ priors) {
    const int b     = blockIdx.x / IOU_NCHUNK;
    const int chunk = blockIdx.x % IOU_NCHUNK;
    const int tid   = threadIdx.x;
    const int lane  = tid & 31;
    const int p     = chunk * IOU_TPB + tid;
    const bool valid = p < P;

    __shared__ float4 sbox[M];
    __shared__ float  sarea[M];
    __shared__ int    s_last;
    if (tid < M) {
        float4 bx = boxes[b * M + tid];
        sbox[tid]  = bx;
        sarea[tid] = (bx.z - bx.x) * (bx.w - bx.y);
    }
    __syncthreads();

    float px0 = 0.f, py0 = 0.f, px1 = 0.f, py1 = 0.f, areap = 0.f;
    if (valid) {
        float4 pc = priors[p];
        px0 = pc.x - pc.z * 0.5f;
        py0 = pc.y - pc.w * 0.5f;
        px1 = pc.x + pc.z * 0.5f;
        py1 = pc.y + pc.w * 0.5f;
        areap = (px1 - px0) * (py1 - py0);
    }

    float bv = -1.0f; int bm = 0;
    #pragma unroll
    for (int m = 0; m < M; m++) {
        float4 bx = sbox[m];
        float iw = fmaxf(fminf(bx.z, px1) - fmaxf(bx.x, px0), 0.0f);
        float ih = fmaxf(fminf(bx.w, py1) - fmaxf(bx.y, py0), 0.0f);
        float inter = iw * ih;
        float iou = valid ? __fdividef(inter, sarea[m] + areap - inter) : 0.0f;
        if (iou > bv) { bv = iou; bm = m; }      // first-max over m
        unsigned int ib = __float_as_uint(iou);  // iou >= 0 -> order-preserving bits
        unsigned int wmax = __reduce_max_sync(0xffffffffu, ib);
        if (wmax) {
            unsigned int mask = __ballot_sync(0xffffffffu, ib == wmax);
            int src = __ffs(mask) - 1;           // smallest lane = smallest prior idx
            if (lane == src) {
                unsigned long long pk =
                    ((unsigned long long)wmax << 32) |
                    (unsigned long long)(~(unsigned int)p);
                atomicMax(&g_best[b * M + m], pk);
            }
        }
    }
    if (valid) {
        g_ovl[b * P + p] = bv;
        g_obj[b * P + p] = (unsigned char)bm;
    }

    // ---- fused: last block does scatter + per-replay resets ----
    __threadfence();
    if (tid == 0) {
        unsigned int t = atomicAdd(&g_iou_done, 1u);
        s_last = (t == IOU_GRID - 1u) ? 1 : 0;
    }
    __syncthreads();
    if (s_last) {
        if (tid < B) {
            const int bb = tid;
            unsigned long long v[M];
            #pragma unroll
            for (int m = 0; m < M; m++) {
                v[m] = g_best[bb * M + m];
                g_best[bb * M + m] = 0ull;        // reset for next replay
            }
            int j = -1;
            #pragma unroll
            for (int m = 0; m < M; m++) {
                if (v[m] >> 32) {  // ovl_obj > 0
                    j++;
                    int pp = (int)(~(unsigned int)(v[m] & 0xffffffffull));
                    g_ovl[bb * P + pp] = 1.0f;
                    g_obj[bb * P + pp] = (unsigned char)j;
                }
            }
            g_conf_pos[bb] = 0.0;
            g_loc_pb[bb]   = 0.0;
            g_n_pos[bb]    = 0;
        }
        if (tid == 0) { g_done = 0u; g_iou_done = 0u; }
        __threadfence();
    }
}

// ---------------- K2: CE loss, block tiles of 64 rows, 4 threads/row, 4-stage cp.async ----------------
#define CT        256
#define CROWS     64
#define CTILE_F   (CROWS * C)        // 5184 floats
#define CTILE_V4  (CTILE_F / 4)      // 1296
#define CSTAGES   4
#define CSMEM     (CSTAGES * CTILE_F * 4)   // 82944 B -> 2 blocks/SM
#define CNT       ((B * P) / CROWS)  // 8732 exact
#define CGRID     296

__global__ void __launch_bounds__(CT, 2)
k_conf(const float4* __restrict__ scores4,
       const float4* __restrict__ locs,
       const int*    __restrict__ labels) {
    extern __shared__ float sm[];
    const int tid  = threadIdx.x;
    const int sub  = tid & 3;
    const int r    = tid >> 2;        // 0..63 row within tile

    // prologue: stage first CSTAGES tiles
    #pragma unroll
    for (int s = 0; s < CSTAGES; s++) {
        int t = blockIdx.x + s * (int)gridDim.x;
        if (t < CNT) {
            const float4* src = scores4 + (size_t)t * CTILE_V4;
            float4* dst = (float4*)(sm + s * CTILE_F);
            for (int i = tid; i < CTILE_V4; i += CT)
                __pipeline_memcpy_async(&dst[i], &src[i], 16);
        }
        __pipeline_commit();
    }

    int it = 0;
    for (int t = blockIdx.x; t < CNT; t += gridDim.x, it++) {
        __pipeline_wait_prior(CSTAGES - 1);
        __syncthreads();
        const float* buf = sm + (it & (CSTAGES - 1)) * CTILE_F;
        const float* rp  = buf + r * C;

        float s = 0.f;
        #pragma unroll
        for (int i = 0; i < 20; i++)
            s += ex2f(rp[sub + 4 * i] * L2E);
        if (sub == 0) s += ex2f(rp[80] * L2E);
        s += __shfl_xor_sync(0xffffffffu, s, 1);
        s += __shfl_xor_sync(0xffffffffu, s, 2);

        if (sub == 0) {
            const int row = t * CROWS + r;
            const int b   = row / P;
            float ou = g_ovl[row];
            int   ob = (int)g_obj[row];
            int tc = (ou < 0.5f) ? 0 : labels[b * M + ob];
            float conf = lg2f(s) * LN2 - rp[tc];   // -(log_softmax[tc]) >= 0
            bool pos = tc > 0;
            g_conf_neg[row] = pos ? 0.0f : conf;
            if (pos) {
                atomicAdd(&g_conf_pos[b], (double)conf);
                atomicAdd(&g_n_pos[b], 1);
                float4 bx = locs[row];
                float iw = fmaxf(bx.z - bx.x, 0.0f);
                float ih = fmaxf(bx.w - bx.y, 0.0f);
                float inter = iw * ih;
                float area = (bx.z - bx.x) * (bx.w - bx.y);
                float iou = __fdividef(inter, area + area - inter + EPSF);
                float dious = fminf(fmaxf(iou, -1.0f), 1.0f);  // inter_diag==0 exactly
                atomicAdd(&g_loc_pb[b], (double)(1.0f - dious));
            }
        }
        __syncthreads();   // everyone done reading buf before restage

        int tn = t + CSTAGES * (int)gridDim.x;
        if (tn < CNT) {
            const float4* src = scores4 + (size_t)tn * CTILE_V4;
            float4* dst = (float4*)(sm + (it & (CSTAGES - 1)) * CTILE_F);
            for (int i = tid; i < CTILE_V4; i += CT)
                __pipeline_memcpy_async(&dst[i], &src[i], 16);
        }
        __pipeline_commit();
    }
}

// ---------------- K3: per-batch top-k sum (smem radix select) + fused final ----------------
__global__ void __launch_bounds__(256)
k_topk(float* __restrict__ out) {
    const int b = blockIdx.x;
    const int tid = threadIdx.x;  // 256
    const int lane = tid & 31;

    __shared__ unsigned int sv[P];     // 34928 B
    __shared__ int hist[256];
    __shared__ int s_bin, s_kk;
    __shared__ int s_last;

    const float* vals = g_conf_neg + b * P;
    for (int p = tid; p < P; p += 256) sv[p] = __float_as_uint(vals[p]);
    __syncthreads();

    long long k = 3LL * (long long)g_n_pos[b];
    double result = 0.0;

    if (k >= P) {
        double sum = 0.0;
        for (int p = tid; p < P; p += 256) sum += (double)__uint_as_float(sv[p]);
        result = blockReduceSumD(sum);
    } else if (k > 0) {
        unsigned int prefix = 0;
        int kk = (int)k;
        for (int pass = 3; pass >= 0; pass--) {
            const int sh_lo = pass * 8;
            hist[tid] = 0;
            __syncthreads();
            for (int base = 0; base < P; base += 256) {
                int p = base + tid;
                bool in = p < P;
                unsigned int v = in ? sv[p] : 0u;
                bool match = in && (pass == 3 || (v >> (sh_lo + 8)) == prefix);
                unsigned int act = __ballot_sync(0xffffffffu, match);
                if (match) {
                    unsigned int bin = (v >> sh_lo) & 255u;
                    unsigned int peers = __match_any_sync(act, bin);
                    if ((__ffs(peers) - 1) == lane)
                        atomicAdd(&hist[bin], (int)__popc(peers));
                }
            }
            __syncthreads();
            int v = hist[tid];
            #pragma unroll
            for (int off = 1; off < 256; off <<= 1) {
                int u = (tid + off < 256) ? hist[tid + off] : 0;
                __syncthreads();
                hist[tid] = v = v + u;
                __syncthreads();
            }
            int cge  = hist[tid];
            int cge1 = (tid < 255) ? hist[tid + 1] : 0;
            if (cge >= kk && (tid == 255 || cge1 < kk)) { s_bin = tid; s_kk = kk - cge1; }
            __syncthreads();
            prefix = (prefix << 8) | (unsigned int)s_bin;
            kk = s_kk;
            __syncthreads();
        }
        unsigned int thr = prefix;
        double sum = 0.0;
        for (int p = tid; p < P; p += 256) {
            unsigned int v = sv[p];
            if (v > thr) sum += (double)__uint_as_float(v);
        }
        result = blockReduceSumD(sum);
        if (tid == 0) result += (double)kk * (double)__uint_as_float(thr);
    }
    if (tid == 0) g_hard_pb[b] = result;

    // ---- fused final: last block combines everything ----
    __threadfence();
    if (tid == 0) {
        unsigned int t = atomicAdd(&g_done, 1u);
        s_last = (t == B - 1u) ? 1 : 0;
    }
    __syncthreads();
    if (s_last) {
        double cp = 0.0, hs = 0.0, ls = 0.0;
        long long np = 0;
        if (tid < B) {
            cp = g_conf_pos[tid];
            hs = g_hard_pb[tid];
            ls = g_loc_pb[tid];
            np = g_n_pos[tid];
        }
        double cps = blockReduceSumD(cp);
        double hss = blockReduceSumD(hs);
        double lss = blockReduceSumD(ls);
        double nps = blockReduceSumD((double)np);
        if (tid == 0) {
            float conf_loss = (float)((hss + cps) / nps);
            float loc_loss  = (float)(lss / fmax(nps, 1.0));
            out[0] = conf_loss + loc_loss;  // ALPHA = 1.0
        }
    }
}

// ---------------- launch ----------------
extern "C" void kernel_launch(void* const* d_in, const int* in_sizes, int n_in,
                              void* d_out, int out_size) {
    const float* locs   = (const float*)d_in[0];  // [B,P,4]
    const float* scores = (const float*)d_in[1];  // [B,P,C]
    const float* boxes  = (const float*)d_in[2];  // [B,M,4]
    const int*   labels = (const int*)  d_in[3];  // [B,M]
    const float* priors = (const float*)d_in[4];  // [P,4]
    float* out = (float*)d_out;

    cudaFuncSetAttribute(k_conf, cudaFuncAttributeMaxDynamicSharedMemorySize, CSMEM);

    k_iou<<<IOU_GRID, IOU_TPB>>>((const float4*)boxes, (const float4*)priors);
    k_conf<<<CGRID, CT, CSMEM>>>((const float4*)scores, (const float4*)locs, labels);
    k_topk<<<B, 256>>>(out);
}

// round 8
// speedup vs baseline: 1.0856x; 1.0856x over previous
#include <cuda_runtime.h>
#include <cuda_pipeline.h>
#include <math.h>

#define B 64
#define P 8732
#define M 16
#define C 81
#define EPSF 1e-7f
#define L2E 1.4426950408889634f
#define LN2 0.6931471805599453f

// ---------------- device scratch ----------------
__device__ float               g_ovl[B * P];
__device__ unsigned char       g_obj[B * P];
__device__ float               g_conf_neg[B * P];
__device__ unsigned long long  g_best[B * M];   // packed (iou_bits<<32)|~prior_idx
__device__ int                 g_n_pos[B];
__device__ double              g_conf_pos[B];
__device__ double              g_loc_pb[B];
__device__ double              g_hard_pb[B];
__device__ unsigned int        g_done;

// ---------------- helpers ----------------
__device__ __forceinline__ float ex2f(float x) {
    float y; asm("ex2.approx.ftz.f32 %0, %1;" : "=f"(y) : "f"(x)); return y;
}
__device__ __forceinline__ float lg2f(float x) {
    float y; asm("lg2.approx.ftz.f32 %0, %1;" : "=f"(y) : "f"(x)); return y;
}

__device__ __forceinline__ double blockReduceSumD(double v) {
    __shared__ double sh[32];
    int lane = threadIdx.x & 31, wid = threadIdx.x >> 5;
    #pragma unroll
    for (int o = 16; o; o >>= 1) v += __shfl_down_sync(0xffffffffu, v, o);
    if (lane == 0) sh[wid] = v;
    __syncthreads();
    int nw = (blockDim.x + 31) >> 5;
    v = (threadIdx.x < (unsigned)nw) ? sh[threadIdx.x] : 0.0;
    if (wid == 0) {
        #pragma unroll
        for (int o = 16; o; o >>= 1) v += __shfl_down_sync(0xffffffffu, v, o);
    }
    __syncthreads();
    return v;  // valid in thread 0
}

// ---------------- K1: per-object best prior (warp per (b,m); no atomics) ----------------
#define OBJ_TPB    256
#define OBJ_GRID   (B * M / 8)       // 128 blocks, 8 warps each
#define OBJ_CHUNK  1024              // priors staged per smem chunk (16 KB)
__global__ void __launch_bounds__(OBJ_TPB)
k_obj(const float4* __restrict__ boxes,
      const float4* __restrict__ priors) {
    const int tid  = threadIdx.x;
    const int wid  = tid >> 5;
    const int lane = tid & 31;
    const int wg   = blockIdx.x * 8 + wid;   // 0..1023
    const int b    = wg >> 4;
    const int m    = wg & 15;

    // per-replay accumulator init (block 0)
    if (blockIdx.x == 0) {
        if (tid < B) { g_conf_pos[tid] = 0.0; g_loc_pb[tid] = 0.0; g_n_pos[tid] = 0; }
        if (tid == B) g_done = 0u;
    }

    __shared__ float4 spri[OBJ_CHUNK];

    float4 bx = boxes[b * M + m];                       // broadcast within warp
    float areab = (bx.z - bx.x) * (bx.w - bx.y);

    unsigned long long vmax = 0ull;
    for (int c0 = 0; c0 < P; c0 += OBJ_CHUNK) {
        int cnt = (c0 + OBJ_CHUNK <= P) ? OBJ_CHUNK : (P - c0);
        __syncthreads();
        for (int i = tid; i < cnt; i += OBJ_TPB) spri[i] = priors[c0 + i];
        __syncthreads();
        for (int j = lane; j < cnt; j += 32) {
            float4 pc = spri[j];
            float px0 = pc.x - pc.z * 0.5f;
            float py0 = pc.y - pc.w * 0.5f;
            float px1 = pc.x + pc.z * 0.5f;
            float py1 = pc.y + pc.w * 0.5f;
            float areap = (px1 - px0) * (py1 - py0);
            float iw = fmaxf(fminf(bx.z, px1) - fmaxf(bx.x, px0), 0.0f);
            float ih = fmaxf(fminf(bx.w, py1) - fmaxf(bx.y, py0), 0.0f);
            float inter = iw * ih;
            float iou = __fdividef(inter, areab + areap - inter);
            int p = c0 + j;
            unsigned long long pk =
                ((unsigned long long)__float_as_uint(iou) << 32) |
                (unsigned long long)(~(unsigned int)p);
            if (pk > vmax) vmax = pk;   // iou>=0 monotone bits; ~p -> smallest p wins ties
        }
    }
    #pragma unroll
    for (int o = 16; o; o >>= 1) {
        unsigned long long u = __shfl_down_sync(0xffffffffu, vmax, o);
        if (u > vmax) vmax = u;
    }
    if (lane == 0) g_best[wg] = vmax;   // exclusive owner, plain store
}

// ---------------- K2: per-prior max over objects + inline scatter override ----------------
#define IOU_TPB    256
#define IOU_NCHUNK ((P + IOU_TPB - 1) / IOU_TPB)   // 35
#define IOU_GRID   (B * IOU_NCHUNK)                 // 2240
__global__ void __launch_bounds__(IOU_TPB)
k_iou(const float4* __restrict__ boxes,
      const float4* __restrict__ priors) {
    const int b     = blockIdx.x / IOU_NCHUNK;
    const int chunk = blockIdx.x % IOU_NCHUNK;
    const int tid   = threadIdx.x;
    const int p0    = chunk * IOU_TPB;
    const int p     = p0 + tid;
    const bool valid = p < P;

    __shared__ float4 sbox[M];
    __shared__ float  sarea[M];
    __shared__ unsigned long long sbest[M];
    __shared__ unsigned char sforce[IOU_TPB];
    if (tid < M) {
        float4 bx = boxes[b * M + tid];
        sbox[tid]  = bx;
        sarea[tid] = (bx.z - bx.x) * (bx.w - bx.y);
        sbest[tid] = g_best[b * M + tid];
    }
    sforce[tid] = 0;
    __syncthreads();
    if (tid == 0) {
        // in-order scatter into the local override table (last-wins by m, faithful j_idx)
        int j = -1;
        #pragma unroll
        for (int m = 0; m < M; m++) {
            unsigned long long v = sbest[m];
            if (v >> 32) {
                j++;
                int pp = (int)(~(unsigned int)(v & 0xffffffffull));
                if (pp >= p0 && pp < p0 + IOU_TPB) sforce[pp - p0] = (unsigned char)(j + 1);
            }
        }
    }
    __syncthreads();

    float px0 = 0.f, py0 = 0.f, px1 = 0.f, py1 = 0.f, areap = 0.f;
    if (valid) {
        float4 pc = priors[p];
        px0 = pc.x - pc.z * 0.5f;
        py0 = pc.y - pc.w * 0.5f;
        px1 = pc.x + pc.z * 0.5f;
        py1 = pc.y + pc.w * 0.5f;
        areap = (px1 - px0) * (py1 - py0);
    }

    float bv = -1.0f; int bm = 0;
    #pragma unroll
    for (int m = 0; m < M; m++) {
        float4 bx = sbox[m];
        float iw = fmaxf(fminf(bx.z, px1) - fmaxf(bx.x, px0), 0.0f);
        float ih = fmaxf(fminf(bx.w, py1) - fmaxf(bx.y, py0), 0.0f);
        float inter = iw * ih;
        float iou = __fdividef(inter, sarea[m] + areap - inter);
        if (iou > bv) { bv = iou; bm = m; }   // first-max over m
    }
    unsigned char f = sforce[tid];
    if (f) { bv = 1.0f; bm = f - 1; }         // override: ovl=1, obj=j (filtered index)
    if (valid) {
        g_ovl[b * P + p] = bv;
        g_obj[b * P + p] = (unsigned char)bm;
    }
}

// ---------------- K3: CE loss, 32-row tiles, 8 threads/row, 4-stage cp.async, 5 blocks/SM ----------------
#define CT        256
#define CROWS     32
#define CTILE_F   (CROWS * C)        // 2592 floats
#define CTILE_V4  (CTILE_F / 4)      // 648
#define CSTAGES   4
#define CSMEM     (CSTAGES * CTILE_F * 4)   // 41472 B
#define CNT       ((B * P) / CROWS)  // 17464 exact
#define CGRID     740

__global__ void __launch_bounds__(CT, 5)
k_conf(const float4* __restrict__ scores4,
       const float4* __restrict__ locs,
       const int*    __restrict__ labels) {
    extern __shared__ float sm[];
    const int tid = threadIdx.x;
    const int sub = tid & 7;
    const int r   = tid >> 3;        // 0..31 row within tile

    #pragma unroll
    for (int s = 0; s < CSTAGES; s++) {
        int t = blockIdx.x + s * CGRID;
        if (t < CNT) {
            const float4* src = scores4 + (size_t)t * CTILE_V4;
            float4* dst = (float4*)(sm + s * CTILE_F);
            for (int i = tid; i < CTILE_V4; i += CT)
                __pipeline_memcpy_async(&dst[i], &src[i], 16);
        }
        __pipeline_commit();
    }

    int it = 0;
    for (int t = blockIdx.x; t < CNT; t += CGRID, it++) {
        __pipeline_wait_prior(CSTAGES - 1);
        __syncthreads();
        const float* rp = sm + (it & (CSTAGES - 1)) * CTILE_F + r * C;

        float s0 = 0.f, s1 = 0.f, s2 = 0.f, s3 = 0.f;
        // elements sub, sub+8, ..., sub+72 (10 per thread) + elem 80 by sub==0
        s0 = ex2f(rp[sub]      * L2E);
        s1 = ex2f(rp[sub + 8]  * L2E);
        s2 = ex2f(rp[sub + 16] * L2E);
        s3 = ex2f(rp[sub + 24] * L2E);
        s0 += ex2f(rp[sub + 32] * L2E);
        s1 += ex2f(rp[sub + 40] * L2E);
        s2 += ex2f(rp[sub + 48] * L2E);
        s3 += ex2f(rp[sub + 56] * L2E);
        s0 += ex2f(rp[sub + 64] * L2E);
        s1 += ex2f(rp[sub + 72] * L2E);
        float s = (s0 + s1) + (s2 + s3);
        if (sub == 0) s += ex2f(rp[80] * L2E);
        s += __shfl_xor_sync(0xffffffffu, s, 1);
        s += __shfl_xor_sync(0xffffffffu, s, 2);
        s += __shfl_xor_sync(0xffffffffu, s, 4);

        if (sub == 0) {
            const int row = t * CROWS + r;
            const int b   = row / P;
            float ou = g_ovl[row];
            int   ob = (int)g_obj[row];
            int tc = (ou < 0.5f) ? 0 : labels[b * M + ob];
            float conf = lg2f(s) * LN2 - rp[tc];   // -(log_softmax[tc]) >= 0
            bool pos = tc > 0;
            g_conf_neg[row] = pos ? 0.0f : conf;
            if (pos) {
                atomicAdd(&g_conf_pos[b], (double)conf);
                atomicAdd(&g_n_pos[b], 1);
                float4 bx = locs[row];
                float iw = fmaxf(bx.z - bx.x, 0.0f);
                float ih = fmaxf(bx.w - bx.y, 0.0f);
                float inter = iw * ih;
                float area = (bx.z - bx.x) * (bx.w - bx.y);
                float iou = __fdividef(inter, area + area - inter + EPSF);
                float dious = fminf(fmaxf(iou, -1.0f), 1.0f);  // inter_diag==0 exactly
                atomicAdd(&g_loc_pb[b], (double)(1.0f - dious));
            }
        }
        __syncthreads();

        int tn = t + CSTAGES * CGRID;
        if (tn < CNT) {
            const float4* src = scores4 + (size_t)tn * CTILE_V4;
            float4* dst = (float4*)(sm + (it & (CSTAGES - 1)) * CTILE_F);
            for (int i = tid; i < CTILE_V4; i += CT)
                __pipeline_memcpy_async(&dst[i], &src[i], 16);
        }
        __pipeline_commit();
    }
}

// ---------------- K4: per-batch top-k sum (smem radix select) + fused final ----------------
__global__ void __launch_bounds__(256)
k_topk(float* __restrict__ out) {
    const int b = blockIdx.x;
    const int tid = threadIdx.x;
    const int lane = tid & 31;

    __shared__ unsigned int sv[P];
    __shared__ int hist[256];
    __shared__ int s_bin, s_kk;
    __shared__ int s_last;

    const float* vals = g_conf_neg + b * P;
    for (int p = tid; p < P; p += 256) sv[p] = __float_as_uint(vals[p]);
    __syncthreads();

    long long k = 3LL * (long long)g_n_pos[b];
    double result = 0.0;

    if (k >= P) {
        double sum = 0.0;
        for (int p = tid; p < P; p += 256) sum += (double)__uint_as_float(sv[p]);
        result = blockReduceSumD(sum);
    } else if (k > 0) {
        unsigned int prefix = 0;
        int kk = (int)k;
        for (int pass = 3; pass >= 0; pass--) {
            const int sh_lo = pass * 8;
            hist[tid] = 0;
            __syncthreads();
            for (int base = 0; base < P; base += 256) {
                int p = base + tid;
                bool in = p < P;
                unsigned int v = in ? sv[p] : 0u;
                bool match = in && (pass == 3 || (v >> (sh_lo + 8)) == prefix);
                unsigned int act = __ballot_sync(0xffffffffu, match);
                if (match) {
                    unsigned int bin = (v >> sh_lo) & 255u;
                    unsigned int peers = __match_any_sync(act, bin);
                    if ((__ffs(peers) - 1) == lane)
                        atomicAdd(&hist[bin], (int)__popc(peers));
                }
            }
            __syncthreads();
            int v = hist[tid];
            #pragma unroll
            for (int off = 1; off < 256; off <<= 1) {
                int u = (tid + off < 256) ? hist[tid + off] : 0;
                __syncthreads();
                hist[tid] = v = v + u;
                __syncthreads();
            }
            int cge  = hist[tid];
            int cge1 = (tid < 255) ? hist[tid + 1] : 0;
            if (cge >= kk && (tid == 255 || cge1 < kk)) { s_bin = tid; s_kk = kk - cge1; }
            __syncthreads();
            prefix = (prefix << 8) | (unsigned int)s_bin;
            kk = s_kk;
            __syncthreads();
        }
        unsigned int thr = prefix;
        double sum = 0.0;
        for (int p = tid; p < P; p += 256) {
            unsigned int v = sv[p];
            if (v > thr) sum += (double)__uint_as_float(v);
        }
        result = blockReduceSumD(sum);
        if (tid == 0) result += (double)kk * (double)__uint_as_float(thr);
    }
    if (tid == 0) g_hard_pb[b] = result;

    // ---- fused final: last block combines everything ----
    __threadfence();
    if (tid == 0) {
        unsigned int t = atomicAdd(&g_done, 1u);
        s_last = (t == B - 1u) ? 1 : 0;
    }
    __syncthreads();
    if (s_last) {
        double cp = 0.0, hs = 0.0, ls = 0.0;
        long long np = 0;
        if (tid < B) {
            cp = g_conf_pos[tid];
            hs = g_hard_pb[tid];
            ls = g_loc_pb[tid];
            np = g_n_pos[tid];
        }
        double cps = blockReduceSumD(cp);
        double hss = blockReduceSumD(hs);
        double lss = blockReduceSumD(ls);
        double nps = blockReduceSumD((double)np);
        if (tid == 0) {
            float conf_loss = (float)((hss + cps) / nps);
            float loc_loss  = (float)(lss / fmax(nps, 1.0));
            out[0] = conf_loss + loc_loss;  // ALPHA = 1.0
        }
    }
}

// ---------------- launch ----------------
extern "C" void kernel_launch(void* const* d_in, const int* in_sizes, int n_in,
                              void* d_out, int out_size) {
    const float* locs   = (const float*)d_in[0];  // [B,P,4]
    const float* scores = (const float*)d_in[1];  // [B,P,C]
    const float* boxes  = (const float*)d_in[2];  // [B,M,4]
    const int*   labels = (const int*)  d_in[3];  // [B,M]
    const float* priors = (const float*)d_in[4];  // [P,4]
    float* out = (float*)d_out;

    cudaFuncSetAttribute(k_conf, cudaFuncAttributeMaxDynamicSharedMemorySize, CSMEM);

    k_obj<<<OBJ_GRID, OBJ_TPB>>>((const float4*)boxes, (const float4*)priors);
    k_iou<<<IOU_GRID, IOU_TPB>>>((const float4*)boxes, (const float4*)priors);
    k_conf<<<CGRID, CT, CSMEM>>>((const float4*)scores, (const float4*)locs, labels);
    k_topk<<<B, 256>>>(out);
}

// round 9
// speedup vs baseline: 1.1711x; 1.0787x over previous
#include <cuda_runtime.h>
#include <cuda_pipeline.h>
#include <math.h>

#define B 64
#define P 8732
#define M 16
#define C 81
#define EPSF 1e-7f
#define L2E 1.4426950408889634f
#define LN2 0.6931471805599453f

// ---------------- device scratch ----------------
__device__ float               g_ovl[B * P];
__device__ unsigned char       g_obj[B * P];
__device__ __align__(16) float g_conf_neg[B * P];
__device__ unsigned long long  g_best[B * M];   // packed (iou_bits<<32)|~prior_idx
__device__ int                 g_n_pos[B];
__device__ double              g_conf_pos[B];
__device__ double              g_loc_pb[B];
__device__ double              g_hard_pb[B];
__device__ unsigned int        g_done;

// ---------------- helpers ----------------
__device__ __forceinline__ float ex2f(float x) {
    float y; asm("ex2.approx.ftz.f32 %0, %1;" : "=f"(y) : "f"(x)); return y;
}
__device__ __forceinline__ float lg2f(float x) {
    float y; asm("lg2.approx.ftz.f32 %0, %1;" : "=f"(y) : "f"(x)); return y;
}

__device__ __forceinline__ double blockReduceSumD(double v) {
    __shared__ double sh[32];
    int lane = threadIdx.x & 31, wid = threadIdx.x >> 5;
    #pragma unroll
    for (int o = 16; o; o >>= 1) v += __shfl_down_sync(0xffffffffu, v, o);
    if (lane == 0) sh[wid] = v;
    __syncthreads();
    int nw = (blockDim.x + 31) >> 5;
    v = (threadIdx.x < (unsigned)nw) ? sh[threadIdx.x] : 0.0;
    if (wid == 0) {
        #pragma unroll
        for (int o = 16; o; o >>= 1) v += __shfl_down_sync(0xffffffffu, v, o);
    }
    __syncthreads();
    return v;  // valid in thread 0
}

// ---------------- K1: per-object best prior (warp per (b,m); no atomics) ----------------
#define OBJ_TPB    256
#define OBJ_GRID   (B * M / 8)       // 128 blocks, 8 warps each
#define OBJ_CHUNK  1024
__global__ void __launch_bounds__(OBJ_TPB)
k_obj(const float4* __restrict__ boxes,
      const float4* __restrict__ priors) {
    const int tid  = threadIdx.x;
    const int wid  = tid >> 5;
    const int lane = tid & 31;
    const int wg   = blockIdx.x * 8 + wid;
    const int b    = wg >> 4;
    const int m    = wg & 15;

    if (blockIdx.x == 0) {
        if (tid < B) { g_conf_pos[tid] = 0.0; g_loc_pb[tid] = 0.0; g_n_pos[tid] = 0; }
        if (tid == B) g_done = 0u;
    }

    __shared__ float4 spri[OBJ_CHUNK];

    float4 bx = boxes[b * M + m];
    float areab = (bx.z - bx.x) * (bx.w - bx.y);

    unsigned long long vmax = 0ull;
    for (int c0 = 0; c0 < P; c0 += OBJ_CHUNK) {
        int cnt = (c0 + OBJ_CHUNK <= P) ? OBJ_CHUNK : (P - c0);
        __syncthreads();
        for (int i = tid; i < cnt; i += OBJ_TPB) spri[i] = priors[c0 + i];
        __syncthreads();
        for (int j = lane; j < cnt; j += 32) {
            float4 pc = spri[j];
            float px0 = pc.x - pc.z * 0.5f;
            float py0 = pc.y - pc.w * 0.5f;
            float px1 = pc.x + pc.z * 0.5f;
            float py1 = pc.y + pc.w * 0.5f;
            float areap = (px1 - px0) * (py1 - py0);
            float iw = fmaxf(fminf(bx.z, px1) - fmaxf(bx.x, px0), 0.0f);
            float ih = fmaxf(fminf(bx.w, py1) - fmaxf(bx.y, py0), 0.0f);
            float inter = iw * ih;
            float iou = __fdividef(inter, areab + areap - inter);
            int p = c0 + j;
            unsigned long long pk =
                ((unsigned long long)__float_as_uint(iou) << 32) |
                (unsigned long long)(~(unsigned int)p);
            if (pk > vmax) vmax = pk;
        }
    }
    #pragma unroll
    for (int o = 16; o; o >>= 1) {
        unsigned long long u = __shfl_down_sync(0xffffffffu, vmax, o);
        if (u > vmax) vmax = u;
    }
    if (lane == 0) g_best[wg] = vmax;
}

// ---------------- K2: per-prior max over objects + inline scatter override ----------------
#define IOU_TPB    256
#define IOU_NCHUNK ((P + IOU_TPB - 1) / IOU_TPB)   // 35
#define IOU_GRID   (B * IOU_NCHUNK)                 // 2240
__global__ void __launch_bounds__(IOU_TPB)
k_iou(const float4* __restrict__ boxes,
      const float4* __restrict__ priors) {
    const int b     = blockIdx.x / IOU_NCHUNK;
    const int chunk = blockIdx.x % IOU_NCHUNK;
    const int tid   = threadIdx.x;
    const int p0    = chunk * IOU_TPB;
    const int p     = p0 + tid;
    const bool valid = p < P;

    __shared__ float4 sbox[M];
    __shared__ float  sarea[M];
    __shared__ unsigned long long sbest[M];
    __shared__ unsigned char sforce[IOU_TPB];
    if (tid < M) {
        float4 bx = boxes[b * M + tid];
        sbox[tid]  = bx;
        sarea[tid] = (bx.z - bx.x) * (bx.w - bx.y);
        sbest[tid] = g_best[b * M + tid];
    }
    sforce[tid] = 0;
    __syncthreads();
    if (tid == 0) {
        int j = -1;
        #pragma unroll
        for (int m = 0; m < M; m++) {
            unsigned long long v = sbest[m];
            if (v >> 32) {
                j++;
                int pp = (int)(~(unsigned int)(v & 0xffffffffull));
                if (pp >= p0 && pp < p0 + IOU_TPB) sforce[pp - p0] = (unsigned char)(j + 1);
            }
        }
    }
    __syncthreads();

    float px0 = 0.f, py0 = 0.f, px1 = 0.f, py1 = 0.f, areap = 0.f;
    if (valid) {
        float4 pc = priors[p];
        px0 = pc.x - pc.z * 0.5f;
        py0 = pc.y - pc.w * 0.5f;
        px1 = pc.x + pc.z * 0.5f;
        py1 = pc.y + pc.w * 0.5f;
        areap = (px1 - px0) * (py1 - py0);
    }

    float bv = -1.0f; int bm = 0;
    #pragma unroll
    for (int m = 0; m < M; m++) {
        float4 bx = sbox[m];
        float iw = fmaxf(fminf(bx.z, px1) - fmaxf(bx.x, px0), 0.0f);
        float ih = fmaxf(fminf(bx.w, py1) - fmaxf(bx.y, py0), 0.0f);
        float inter = iw * ih;
        float iou = __fdividef(inter, sarea[m] + areap - inter);
        if (iou > bv) { bv = iou; bm = m; }
    }
    unsigned char f = sforce[tid];
    if (f) { bv = 1.0f; bm = f - 1; }
    if (valid) {
        g_ovl[b * P + p] = bv;
        g_obj[b * P + p] = (unsigned char)bm;
    }
}

// ---------------- K3: CE loss, 32-row tiles, 8 threads/row, 3-stage cp.async, 6 blocks/SM ----------------
#define CT        256
#define CROWS     32
#define CTILE_F   (CROWS * C)        // 2592 floats
#define CTILE_V4  (CTILE_F / 4)      // 648
#define CSTAGES   3
#define CSMEM     (CSTAGES * CTILE_F * 4)   // 31104 B
#define CNT       ((B * P) / CROWS)  // 17464 exact
#define CGRID     888

__global__ void __launch_bounds__(CT, 6)
k_conf(const float4* __restrict__ scores4,
       const float4* __restrict__ locs,
       const int*    __restrict__ labels) {
    extern __shared__ float sm[];
    const int tid = threadIdx.x;
    const int sub = tid & 7;
    const int r   = tid >> 3;

    #pragma unroll
    for (int s = 0; s < CSTAGES; s++) {
        int t = blockIdx.x + s * CGRID;
        if (t < CNT) {
            const float4* src = scores4 + (size_t)t * CTILE_V4;
            float4* dst = (float4*)(sm + s * CTILE_F);
            for (int i = tid; i < CTILE_V4; i += CT)
                __pipeline_memcpy_async(&dst[i], &src[i], 16);
        }
        __pipeline_commit();
    }

    int it = 0;
    for (int t = blockIdx.x; t < CNT; t += CGRID, it++) {
        __pipeline_wait_prior(CSTAGES - 1);
        __syncthreads();
        int slot = it % CSTAGES;
        const float* rp = sm + slot * CTILE_F + r * C;

        float s0, s1, s2, s3;
        s0 = ex2f(rp[sub]      * L2E);
        s1 = ex2f(rp[sub + 8]  * L2E);
        s2 = ex2f(rp[sub + 16] * L2E);
        s3 = ex2f(rp[sub + 24] * L2E);
        s0 += ex2f(rp[sub + 32] * L2E);
        s1 += ex2f(rp[sub + 40] * L2E);
        s2 += ex2f(rp[sub + 48] * L2E);
        s3 += ex2f(rp[sub + 56] * L2E);
        s0 += ex2f(rp[sub + 64] * L2E);
        s1 += ex2f(rp[sub + 72] * L2E);
        float s = (s0 + s1) + (s2 + s3);
        if (sub == 0) s += ex2f(rp[80] * L2E);
        s += __shfl_xor_sync(0xffffffffu, s, 1);
        s += __shfl_xor_sync(0xffffffffu, s, 2);
        s += __shfl_xor_sync(0xffffffffu, s, 4);

        if (sub == 0) {
            const int row = t * CROWS + r;
            const int b   = row / P;
            float ou = g_ovl[row];
            int   ob = (int)g_obj[row];
            int tc = (ou < 0.5f) ? 0 : labels[b * M + ob];
            float conf = lg2f(s) * LN2 - rp[tc];
            bool pos = tc > 0;
            g_conf_neg[row] = pos ? 0.0f : conf;
            if (pos) {
                atomicAdd(&g_conf_pos[b], (double)conf);
                atomicAdd(&g_n_pos[b], 1);
                float4 bx = locs[row];
                float iw = fmaxf(bx.z - bx.x, 0.0f);
                float ih = fmaxf(bx.w - bx.y, 0.0f);
                float inter = iw * ih;
                float area = (bx.z - bx.x) * (bx.w - bx.y);
                float iou = __fdividef(inter, area + area - inter + EPSF);
                float dious = fminf(fmaxf(iou, -1.0f), 1.0f);
                atomicAdd(&g_loc_pb[b], (double)(1.0f - dious));
            }
        }
        __syncthreads();

        int tn = t + CSTAGES * CGRID;
        if (tn < CNT) {
            const float4* src = scores4 + (size_t)tn * CTILE_V4;
            float4* dst = (float4*)(sm + slot * CTILE_F);
            for (int i = tid; i < CTILE_V4; i += CT)
                __pipeline_memcpy_async(&dst[i], &src[i], 16);
        }
        __pipeline_commit();
    }
}

// ---------------- K4: per-batch top-k sum, 1024 threads, warp-scan histogram ----------------
#define TKT 1024
__global__ void __launch_bounds__(TKT)
k_topk(float* __restrict__ out) {
    const int b    = blockIdx.x;
    const int tid  = threadIdx.x;
    const int lane = tid & 31;
    const int wid  = tid >> 5;

    __shared__ unsigned int sv[P];     // 34928 B
    __shared__ int hist[256];
    __shared__ int s_bin, s_kk;
    __shared__ int s_last;

    // cache values (uint4 loads; P % 4 == 0)
    {
        const uint4* src = (const uint4*)(g_conf_neg + b * P);
        uint4* dst = (uint4*)sv;
        for (int i = tid; i < P / 4; i += TKT) dst[i] = src[i];
    }
    __syncthreads();

    long long k = 3LL * (long long)g_n_pos[b];
    double result = 0.0;

    if (k >= P) {
        double sum = 0.0;
        for (int p = tid; p < P; p += TKT) sum += (double)__uint_as_float(sv[p]);
        result = blockReduceSumD(sum);
    } else if (k > 0) {
        unsigned int prefix = 0;
        int kk = (int)k;
        for (int pass = 3; pass >= 0; pass--) {
            const int sh_lo = pass * 8;
            if (tid < 256) hist[tid] = 0;
            __syncthreads();
            // warp-aggregated histogram, uniform trip count
            for (int base = 0; base < P; base += TKT) {
                int p = base + tid;
                bool in = p < P;
                unsigned int v = in ? sv[p] : 0u;
                bool match = in && (pass == 3 || (v >> (sh_lo + 8)) == prefix);
                unsigned int act = __ballot_sync(0xffffffffu, match);
                if (match) {
                    unsigned int bin = (v >> sh_lo) & 255u;
                    unsigned int peers = __match_any_sync(act, bin);
                    if ((__ffs(peers) - 1) == lane)
                        atomicAdd(&hist[bin], (int)__popc(peers));
                }
            }
            __syncthreads();
            // warp-0 suffix scan over 256 bins (8 bins per lane)
            if (wid == 0) {
                int base = lane * 8;
                int h0 = hist[base],     h1 = hist[base + 1];
                int h2 = hist[base + 2], h3 = hist[base + 3];
                int h4 = hist[base + 4], h5 = hist[base + 5];
                int h6 = hist[base + 6], h7 = hist[base + 7];
                int ss7 = h7;
                int ss6 = ss7 + h6, ss5 = ss6 + h5, ss4 = ss5 + h4;
                int ss3 = ss4 + h3, ss2 = ss3 + h2, ss1 = ss2 + h1;
                int ss0 = ss1 + h0;
                int S = ss0;  // lane total
                #pragma unroll
                for (int off = 1; off < 32; off <<= 1) {
                    int u = __shfl_down_sync(0xffffffffu, S, off);
                    if (lane + off < 32) S += u;
                }
                int A = S - ss0;   // sum of lanes > lane
                int cge[9] = { ss0 + A, ss1 + A, ss2 + A, ss3 + A,
                               ss4 + A, ss5 + A, ss6 + A, ss7 + A, A };
                #pragma unroll
                for (int j = 0; j < 8; j++) {
                    if (cge[j] >= kk && cge[j + 1] < kk) {
                        s_bin = base + j;
                        s_kk  = kk - cge[j + 1];
                    }
                }
            }
            __syncthreads();
            prefix = (prefix << 8) | (unsigned int)s_bin;
            kk = s_kk;
        }
        // kk copies of the threshold value; everything strictly above included
        unsigned int thr = prefix;
        double sum = 0.0;
        for (int p = tid; p < P; p += TKT) {
            unsigned int v = sv[p];
            if (v > thr) sum += (double)__uint_as_float(v);
        }
        result = blockReduceSumD(sum);
        if (tid == 0) result += (double)kk * (double)__uint_as_float(thr);
    }
    if (tid == 0) g_hard_pb[b] = result;

    // ---- fused final: last block combines everything ----
    __threadfence();
    if (tid == 0) {
        unsigned int t = atomicAdd(&g_done, 1u);
        s_last = (t == B - 1u) ? 1 : 0;
    }
    __syncthreads();
    if (s_last) {
        double cp = 0.0, hs = 0.0, ls = 0.0;
        long long np = 0;
        if (tid < B) {
            cp = g_conf_pos[tid];
            hs = g_hard_pb[tid];
            ls = g_loc_pb[tid];
            np = g_n_pos[tid];
        }
        double cps = blockReduceSumD(cp);
        double hss = blockReduceSumD(hs);
        double lss = blockReduceSumD(ls);
        double nps = blockReduceSumD((double)np);
        if (tid == 0) {
            float conf_loss = (float)((hss + cps) / nps);
            float loc_loss  = (float)(lss / fmax(nps, 1.0));
            out[0] = conf_loss + loc_loss;  // ALPHA = 1.0
        }
    }
}

// ---------------- launch ----------------
extern "C" void kernel_launch(void* const* d_in, const int* in_sizes, int n_in,
                              void* d_out, int out_size) {
    const float* locs   = (const float*)d_in[0];  // [B,P,4]
    const float* scores = (const float*)d_in[1];  // [B,P,C]
    const float* boxes  = (const float*)d_in[2];  // [B,M,4]
    const int*   labels = (const int*)  d_in[3];  // [B,M]
    const float* priors = (const float*)d_in[4];  // [P,4]
    float* out = (float*)d_out;

    cudaFuncSetAttribute(k_conf, cudaFuncAttributeMaxDynamicSharedMemorySize, CSMEM);

    k_obj<<<OBJ_GRID, OBJ_TPB>>>((const float4*)boxes, (const float4*)priors);
    k_iou<<<IOU_GRID, IOU_TPB>>>((const float4*)boxes, (const float4*)priors);
    k_conf<<<CGRID, CT, CSMEM>>>((const float4*)scores, (const float4*)locs, labels);
    k_topk<<<B, TKT>>>(out);
}